// round 11
// baseline (speedup 1.0000x reference)
#include <cuda_runtime.h>
#include <cstdint>

// out[b,p,d] = (sum_h hs[b,p,h] * W[prop[b,p], h, d] + bias[prop[b,p], d]) * mask[b,p]
// B=512, P=128 -> 65536 rows, H=512, D=2.
//
// L2/LTS-traffic optimization: counting-sort row indices by property so that
// rows sharing a property land in the same CTA -> W row is fetched from L2
// once per CTA and served from L1 for sibling warps. Cuts W L2 traffic ~4x.
// Pipeline: zero-hist -> histogram -> scan(1 block) -> scatter -> main (R7-style
// cp.async staging, one row per warp, row = perm[task]).

#define NROWS 65536
#define NPROPS 10000
#define HDIM 512
#define WPB 8

__device__ int g_hist[NPROPS];
__device__ int g_cursor[NPROPS];
__device__ int g_perm[NROWS];

__global__ void zero_hist_kernel() {
    int i = blockIdx.x * blockDim.x + threadIdx.x;
    if (i < NPROPS) g_hist[i] = 0;
}

__global__ void hist_kernel(const int* __restrict__ props) {
    int r = blockIdx.x * blockDim.x + threadIdx.x;
    if (r < NROWS) atomicAdd(&g_hist[props[r]], 1);
}

// Exclusive scan of g_hist[10000] -> g_cursor. One block, 1024 threads, 10 elems/thread.
__global__ __launch_bounds__(1024) void scan_kernel() {
    __shared__ int tmp[1024];
    const int tid = threadIdx.x;
    const int base = tid * 10;

    int local[10];
    int s = 0;
    #pragma unroll
    for (int i = 0; i < 10; i++) {
        int idx = base + i;
        int v = (idx < NPROPS) ? g_hist[idx] : 0;
        local[i] = s;
        s += v;
    }
    tmp[tid] = s;
    __syncthreads();
    for (int off = 1; off < 1024; off <<= 1) {
        int v = (tid >= off) ? tmp[tid - off] : 0;
        __syncthreads();
        tmp[tid] += v;
        __syncthreads();
    }
    const int excl = (tid == 0) ? 0 : tmp[tid - 1];
    #pragma unroll
    for (int i = 0; i < 10; i++) {
        int idx = base + i;
        if (idx < NPROPS) g_cursor[idx] = excl + local[i];
    }
}

__global__ void scatter_kernel(const int* __restrict__ props) {
    int r = blockIdx.x * blockDim.x + threadIdx.x;
    if (r < NROWS) {
        int p = props[r];
        int pos = atomicAdd(&g_cursor[p], 1);
        g_perm[pos] = r;
    }
}

// Main: one row per warp, rows taken in property-sorted order.
__global__ __launch_bounds__(32 * WPB) void adapter_kernel(
    const float* __restrict__ hs,          // [65536, 512]
    const int* __restrict__ props,         // [65536] int32
    const float* __restrict__ mask,        // [65536]
    const float* __restrict__ W,           // [10000, 512, 2]
    const float* __restrict__ bias,        // [10000, 2]
    float* __restrict__ out)               // [65536, 2]
{
    __shared__ float4 hbuf[WPB][128];   // 2KB per warp
    __shared__ float4 wbuf[WPB][256];   // 4KB per warp

    const int warp = threadIdx.x >> 5;
    const int lane = threadIdx.x & 31;
    const int task = blockIdx.x * WPB + warp;
    const int row  = g_perm[task];          // property-sorted order

    const int p = __ldg(&props[row]);

    const float4* __restrict__ h4 = reinterpret_cast<const float4*>(hs + (size_t)row * HDIM);
    const float4* __restrict__ w4 = reinterpret_cast<const float4*>(W + (size_t)p * (HDIM * 2));

    // Evict-first policy for the hs stream (protects W residency in L2).
    uint64_t pol;
    asm volatile("createpolicy.fractional.L2::evict_first.b64 %0, 1.0;" : "=l"(pol));

    // hs: 4 x 16B per lane, coalesced, streamed.
    #pragma unroll
    for (int i = 0; i < 4; i++) {
        uint32_t dst = (uint32_t)__cvta_generic_to_shared(&hbuf[warp][i * 32 + lane]);
        asm volatile("cp.async.cg.shared.global.L2::cache_hint [%0], [%1], 16, %2;"
                     :: "r"(dst), "l"(h4 + i * 32 + lane), "l"(pol) : "memory");
    }
    // W: 8 x 16B per lane, coalesced, default (cached) policy -> L1-served for
    // sibling warps with the same property.
    #pragma unroll
    for (int i = 0; i < 8; i++) {
        uint32_t dst = (uint32_t)__cvta_generic_to_shared(&wbuf[warp][i * 32 + lane]);
        asm volatile("cp.async.cg.shared.global [%0], [%1], 16;"
                     :: "r"(dst), "l"(w4 + i * 32 + lane) : "memory");
    }
    asm volatile("cp.async.commit_group;" ::: "memory");
    asm volatile("cp.async.wait_group 0;" ::: "memory");
    __syncwarp();

    // Consume: W linear (LDS.128), hs as float2 (stride-8B, conflict-free).
    // wbuf[idx] = (W[h,0], W[h,1], W[h+1,0], W[h+1,1]) for h = 2*idx.
    const float2* __restrict__ h2 = reinterpret_cast<const float2*>(hbuf[warp]);

    float acc0 = 0.f, acc1 = 0.f;
    #pragma unroll
    for (int j = 0; j < 8; j++) {
        const int idx = j * 32 + lane;
        const float4 wv = wbuf[warp][idx];
        const float2 hh = h2[idx];
        acc0 = fmaf(hh.x, wv.x, acc0);
        acc1 = fmaf(hh.x, wv.y, acc1);
        acc0 = fmaf(hh.y, wv.z, acc0);
        acc1 = fmaf(hh.y, wv.w, acc1);
    }

    #pragma unroll
    for (int off = 16; off > 0; off >>= 1) {
        acc0 += __shfl_xor_sync(0xFFFFFFFFu, acc0, off);
        acc1 += __shfl_xor_sync(0xFFFFFFFFu, acc1, off);
    }

    if (lane == 0) {
        const float m = mask[row];
        const float b0 = __ldg(&bias[p * 2 + 0]);
        const float b1 = __ldg(&bias[p * 2 + 1]);
        float2 r;
        r.x = (acc0 + b0) * m;
        r.y = (acc1 + b1) * m;
        __stcs(reinterpret_cast<float2*>(out) + row, r);
    }
}

extern "C" void kernel_launch(void* const* d_in, const int* in_sizes, int n_in,
                              void* d_out, int out_size)
{
    const float* hs    = (const float*)d_in[0];
    const int*   props = (const int*)d_in[1];
    const float* mask  = (const float*)d_in[2];
    const float* W     = (const float*)d_in[3];
    const float* bias  = (const float*)d_in[4];
    float*       out   = (float*)d_out;

    zero_hist_kernel<<<(NPROPS + 255) / 256, 256>>>();
    hist_kernel<<<NROWS / 256, 256>>>(props);
    scan_kernel<<<1, 1024>>>();
    scatter_kernel<<<NROWS / 256, 256>>>(props);

    const int threads = 32 * WPB;
    const int blocks = NROWS / WPB;
    adapter_kernel<<<blocks, threads>>>(hs, props, mask, W, bias, out);
}

// round 12
// speedup vs baseline: 1.6993x; 1.6993x over previous
#include <cuda_runtime.h>
#include <cstdint>

// out[b,p,d] = (sum_h hs[b,p,h] * W[prop[b,p], h, d] + bias[prop[b,p], d]) * mask[b,p]
// B=512, P=128 -> 65536 rows, H=512, D=2. One warp per row (R7 architecture).
// Both operand rows staged via cp.async.cg (no register residency in flight):
//   hs row (2KB, DRAM stream)  -> L2::evict_first (never pollutes L2)
//   W  row (4KB, L2 gather)    -> L2::evict_last  (stays resident, 41MB table)
// WPB=2 (12KB smem/block) -> 19 blocks/SM, 38 resident warps.

#define NROWS 65536
#define HDIM 512
#define WPB 2

__global__ __launch_bounds__(32 * WPB) void adapter_kernel(
    const float* __restrict__ hs,          // [65536, 512]
    const int* __restrict__ props,         // [65536] int32
    const float* __restrict__ mask,        // [65536]
    const float* __restrict__ W,           // [10000, 512, 2]
    const float* __restrict__ bias,        // [10000, 2]
    float* __restrict__ out)               // [65536, 2]
{
    __shared__ float4 hbuf[WPB][128];   // 2KB per warp
    __shared__ float4 wbuf[WPB][256];   // 4KB per warp

    const int warp = threadIdx.x >> 5;
    const int lane = threadIdx.x & 31;
    const int row = blockIdx.x * WPB + warp;

    const int p = __ldg(&props[row]);

    const float4* __restrict__ h4 = reinterpret_cast<const float4*>(hs + (size_t)row * HDIM);
    const float4* __restrict__ w4 = reinterpret_cast<const float4*>(W + (size_t)p * (HDIM * 2));

    // L2 policies: hs = evict_first (stream), W = evict_last (keep resident).
    uint64_t pol_first, pol_last;
    asm volatile("createpolicy.fractional.L2::evict_first.b64 %0, 1.0;" : "=l"(pol_first));
    asm volatile("createpolicy.fractional.L2::evict_last.b64 %0, 1.0;" : "=l"(pol_last));

    // hs: 4 x 16B per lane, coalesced, streamed (addresses independent of p).
    #pragma unroll
    for (int i = 0; i < 4; i++) {
        uint32_t dst = (uint32_t)__cvta_generic_to_shared(&hbuf[warp][i * 32 + lane]);
        asm volatile("cp.async.cg.shared.global.L2::cache_hint [%0], [%1], 16, %2;"
                     :: "r"(dst), "l"(h4 + i * 32 + lane), "l"(pol_first) : "memory");
    }
    // W: 8 x 16B per lane, coalesced, pinned-ish in L2.
    #pragma unroll
    for (int i = 0; i < 8; i++) {
        uint32_t dst = (uint32_t)__cvta_generic_to_shared(&wbuf[warp][i * 32 + lane]);
        asm volatile("cp.async.cg.shared.global.L2::cache_hint [%0], [%1], 16, %2;"
                     :: "r"(dst), "l"(w4 + i * 32 + lane), "l"(pol_last) : "memory");
    }
    asm volatile("cp.async.commit_group;" ::: "memory");
    asm volatile("cp.async.wait_group 0;" ::: "memory");
    __syncwarp();   // consume reads cross-lane copies

    // Consume: W linear (conflict-free LDS.128), hs as float2 (stride-8B,
    // conflict-free LDS.64). wbuf[idx] = (W[h,0],W[h,1],W[h+1,0],W[h+1,1]), h=2*idx.
    const float2* __restrict__ h2 = reinterpret_cast<const float2*>(hbuf[warp]);

    float acc0 = 0.f, acc1 = 0.f;
    #pragma unroll
    for (int j = 0; j < 8; j++) {
        const int idx = j * 32 + lane;
        const float4 wv = wbuf[warp][idx];
        const float2 hh = h2[idx];
        acc0 = fmaf(hh.x, wv.x, acc0);
        acc1 = fmaf(hh.x, wv.y, acc1);
        acc0 = fmaf(hh.y, wv.z, acc0);
        acc1 = fmaf(hh.y, wv.w, acc1);
    }

    // Warp tree reduction (two independent chains, interleaved by scheduler)
    #pragma unroll
    for (int off = 16; off > 0; off >>= 1) {
        acc0 += __shfl_xor_sync(0xFFFFFFFFu, acc0, off);
        acc1 += __shfl_xor_sync(0xFFFFFFFFu, acc1, off);
    }

    if (lane == 0) {
        const float m = mask[row];
        const float b0 = __ldg(&bias[p * 2 + 0]);
        const float b1 = __ldg(&bias[p * 2 + 1]);
        float2 r;
        r.x = (acc0 + b0) * m;
        r.y = (acc1 + b1) * m;
        __stcs(reinterpret_cast<float2*>(out) + row, r);
    }
}

extern "C" void kernel_launch(void* const* d_in, const int* in_sizes, int n_in,
                              void* d_out, int out_size)
{
    const float* hs    = (const float*)d_in[0];
    const int*   props = (const int*)d_in[1];
    const float* mask  = (const float*)d_in[2];
    const float* W     = (const float*)d_in[3];
    const float* bias  = (const float*)d_in[4];
    float*       out   = (float*)d_out;

    const int threads = 32 * WPB;
    const int blocks = NROWS / WPB;
    adapter_kernel<<<blocks, threads>>>(hs, props, mask, W, bias, out);
}